// round 2
// baseline (speedup 1.0000x reference)
#include <cuda_runtime.h>
#include <math.h>

#define WIDTH   128
#define HEIGHT  128
#define NPIX    (WIDTH * HEIGHT)
#define NEARP   0.1f
#define FARP    10.0f
#define EPSV    1e-8f

#define VMAX    4096
#define FMAX    4096
#define CHUNK   256
#define MAXCHUNKS (FMAX / CHUNK)

// ---------------- scratch (device globals; no allocation allowed) ----------
__device__ float g_vx[VMAX], g_vy[VMAX], g_vz[VMAX], g_viw[VMAX];
__device__ int   g_vvalid[VMAX];
__device__ float4 g_t0[FMAX];   // ax, ay, bx, by
__device__ float4 g_t1[FMAX];   // cx, cy, za, zb
__device__ float2 g_t2[FMAX];   // zc, inv_area
__device__ unsigned long long g_part[MAXCHUNKS][NPIX];

__device__ __forceinline__ float f_nan() { return __int_as_float(0x7fc00000); }
__device__ __forceinline__ float f_inf() { return __int_as_float(0x7f800000); }

// ---------------- kernel 1: camera matrices + vertex transform -------------
__global__ void vertex_kernel(const float* __restrict__ v,
                              const float* __restrict__ camf,
                              const float* __restrict__ camc,
                              const float* __restrict__ camt,
                              const float* __restrict__ camrt,
                              int V)
{
    __shared__ float M[4][4];
    if (threadIdx.x == 0) {
        // ---- perspective (m, then transposed) ----
        float f   = 0.5f * (camf[0] + camf[1]);
        float ccx = camc[0], ccy = camc[1];
        float nf  = NEARP / f;
        float right = ((float)WIDTH - (ccx + 0.5f)) * nf;
        float left  = -(ccx + 0.5f) * nf;
        float top   = (ccy + 0.5f) * nf;
        float bot   = -((float)HEIGHT - ccy + 0.5f) * nf;
        float m[4][4];
        #pragma unroll
        for (int i = 0; i < 4; i++)
            #pragma unroll
            for (int j = 0; j < 4; j++) m[i][j] = 0.0f;
        m[0][0] = 2.0f * NEARP / (right - left); m[0][2] = (right + left) / (right - left);
        m[1][1] = 2.0f * NEARP / (top - bot);    m[1][2] = (top + bot) / (top - bot);
        m[2][2] = -(FARP + NEARP) / (FARP - NEARP);
        m[2][3] = -2.0f * FARP * NEARP / (FARP - NEARP);
        m[3][2] = -1.0f;
        float P[4][4];
        #pragma unroll
        for (int i = 0; i < 4; i++)
            #pragma unroll
            for (int j = 0; j < 4; j++) P[i][j] = m[j][i];

        // ---- rodrigues ----
        float rx = camrt[0], ry = camrt[1], rz = camrt[2];
        float th = sqrtf(rx * rx + ry * ry + rz * rz + 1e-12f);
        float kx = rx / th, ky = ry / th, kz = rz / th;
        float s  = sinf(th);
        float cc = 1.0f - cosf(th);
        float K[3][3] = {{0.f, -kz, ky}, {kz, 0.f, -kx}, {-ky, kx, 0.f}};
        float K2[3][3];
        #pragma unroll
        for (int i = 0; i < 3; i++)
            #pragma unroll
            for (int j = 0; j < 3; j++) {
                float acc = 0.f;
                #pragma unroll
                for (int k = 0; k < 3; k++) acc += K[i][k] * K[k][j];
                K2[i][j] = acc;
            }
        float R[3][3];
        #pragma unroll
        for (int i = 0; i < 3; i++)
            #pragma unroll
            for (int j = 0; j < 3; j++)
                R[i][j] = (i == j ? 1.0f : 0.0f) + s * K[i][j] + cc * K2[i][j];

        // ---- view = Mr @ Mt ----
        float Vw[4][4];
        #pragma unroll
        for (int i = 0; i < 4; i++)
            #pragma unroll
            for (int j = 0; j < 4; j++) Vw[i][j] = 0.0f;
        #pragma unroll
        for (int i = 0; i < 3; i++)
            #pragma unroll
            for (int j = 0; j < 3; j++) Vw[i][j] = R[j][i];   // R.T
        Vw[3][0] = camt[0]; Vw[3][1] = camt[1]; Vw[3][2] = camt[2];
        Vw[3][3] = 1.0f;

        // ---- M = view @ proj ----
        #pragma unroll
        for (int i = 0; i < 4; i++)
            #pragma unroll
            for (int j = 0; j < 4; j++) {
                float acc = 0.f;
                #pragma unroll
                for (int k = 0; k < 4; k++) acc += Vw[i][k] * P[k][j];
                M[i][j] = acc;
            }
    }
    __syncthreads();

    for (int i = threadIdx.x; i < V; i += blockDim.x) {
        float x = v[3 * i], y = v[3 * i + 1], z = v[3 * i + 2];
        float c0 = x * M[0][0] + y * M[1][0] + z * M[2][0] + M[3][0];
        float c1 = x * M[0][1] + y * M[1][1] + z * M[2][1] + M[3][1];
        float c2 = x * M[0][2] + y * M[1][2] + z * M[2][2] + M[3][2];
        float c3 = x * M[0][3] + y * M[1][3] + z * M[2][3] + M[3][3];
        int valid = (c3 > EPSV) ? 1 : 0;
        float ws = valid ? c3 : 1.0f;
        float nx = c0 / ws, ny = c1 / ws, nz = c2 / ws;
        g_vx[i]  = (nx * 0.5f + 0.5f) * (float)WIDTH;
        g_vy[i]  = (0.5f - ny * 0.5f) * (float)HEIGHT;
        g_vz[i]  = nz;
        g_viw[i] = 1.0f / ws;
        g_vvalid[i] = valid;
    }
}

// ---------------- kernel 2: per-triangle setup -----------------------------
__global__ void tri_kernel(const int* __restrict__ f, int F)
{
    int t = blockIdx.x * blockDim.x + threadIdx.x;
    if (t >= F) return;
    int i0 = f[3 * t], i1 = f[3 * t + 1], i2 = f[3 * t + 2];
    float ax = g_vx[i0], ay = g_vy[i0];
    float bx = g_vx[i1], by = g_vy[i1];
    float cx = g_vx[i2], cy = g_vy[i2];
    float area = (bx - ax) * (cy - ay) - (by - ay) * (cx - ax);
    bool areaok = fabsf(area) > EPSV;
    bool ok = areaok && g_vvalid[i0] && g_vvalid[i1] && g_vvalid[i2];
    float area_safe = areaok ? area : 1.0f;
    float inva = 1.0f / area_safe;
    float za = ok ? g_vz[i0] : f_nan();
    float zb = ok ? g_vz[i1] : f_nan();
    float zc = ok ? g_vz[i2] : f_nan();
    g_t0[t] = make_float4(ax, ay, bx, by);
    g_t1[t] = make_float4(cx, cy, za, zb);
    g_t2[t] = make_float2(zc, inva);
}

// ---------------- kernel 3: chunked rasterization --------------------------
__global__ void raster_kernel(int F)
{
    __shared__ float4 s0[CHUNK];
    __shared__ float4 s1[CHUNK];
    __shared__ float2 s2[CHUNK];

    int chunk = blockIdx.y;
    int tbase = chunk * CHUNK;
    int nt = F - tbase;
    if (nt > CHUNK) nt = CHUNK;

    for (int i = threadIdx.x; i < nt; i += blockDim.x) {
        s0[i] = g_t0[tbase + i];
        s1[i] = g_t1[tbase + i];
        s2[i] = g_t2[tbase + i];
    }
    __syncthreads();

    int p = blockIdx.x * blockDim.x + threadIdx.x;
    float px = (float)(p % WIDTH) + 0.5f;
    float py = (float)(p / WIDTH) + 0.5f;

    float bestz = f_inf();
    int   besti = tbase;

    #pragma unroll 4
    for (int i = 0; i < nt; i++) {
        float4 q0 = s0[i];
        float4 q1 = s1[i];
        float2 q2 = s2[i];
        // same expressions as reference E(p,q)
        float w0 = (q1.x - q0.z) * (py - q0.w) - (q1.y - q0.w) * (px - q0.z); // E(b,c)
        float w1 = (q0.x - q1.x) * (py - q1.y) - (q0.y - q1.y) * (px - q1.x); // E(c,a)
        float w2 = (q0.z - q0.x) * (py - q0.y) - (q0.w - q0.y) * (px - q0.x); // E(a,b)
        float b0 = w0 * q2.y;
        float b1 = w1 * q2.y;
        float b2 = w2 * q2.y;
        float z  = b0 * q1.z + b1 * q1.w + b2 * q2.x;  // NaN if invalid tri
        bool inside = (b0 >= 0.0f) & (b1 >= 0.0f) & (b2 >= 0.0f) &
                      (z >= -1.0f) & (z <= 1.0f);
        if (inside && (z < bestz)) { bestz = z; besti = tbase + i; }
    }

    // sortable float encoding: monotone in depth, inf for "none"
    unsigned int d = __float_as_uint(bestz);
    d = (d & 0x80000000u) ? ~d : (d | 0x80000000u);
    g_part[chunk][p] = ((unsigned long long)d << 32) | (unsigned int)besti;
}

// ---------------- kernel 4: reduce + shade ---------------------------------
__global__ void shade_kernel(const int* __restrict__ f,
                             const float* __restrict__ vc,
                             const float* __restrict__ bg,
                             float* __restrict__ out,
                             int nchunks)
{
    int p = blockIdx.x * blockDim.x + threadIdx.x;
    if (p >= NPIX) return;

    unsigned long long best = g_part[0][p];
    for (int c = 1; c < nchunks; c++) {
        unsigned long long k = g_part[c][p];
        if (k < best) best = k;
    }
    unsigned int d = (unsigned int)(best >> 32);
    unsigned int one_enc = __float_as_uint(1.0f) | 0x80000000u;

    float r, g, bl;
    if (d <= one_enc) {
        int t = (int)(unsigned int)(best & 0xffffffffu);
        float4 q0 = g_t0[t];
        float4 q1 = g_t1[t];
        float2 q2 = g_t2[t];
        float px = (float)(p % WIDTH) + 0.5f;
        float py = (float)(p / WIDTH) + 0.5f;
        float w0 = (q1.x - q0.z) * (py - q0.w) - (q1.y - q0.w) * (px - q0.z);
        float w1 = (q0.x - q1.x) * (py - q1.y) - (q0.y - q1.y) * (px - q1.x);
        float w2 = (q0.z - q0.x) * (py - q0.y) - (q0.w - q0.y) * (px - q0.x);
        float b0 = w0 * q2.y;
        float b1 = w1 * q2.y;
        float b2 = w2 * q2.y;
        int i0 = f[3 * t], i1 = f[3 * t + 1], i2 = f[3 * t + 2];
        float g0 = b0 * g_viw[i0];
        float g1 = b1 * g_viw[i1];
        float g2 = b2 * g_viw[i2];
        float den = g0 + g1 + g2;
        den = (fabsf(den) > EPSV) ? den : 1.0f;
        r  = (g0 * vc[3 * i0 + 0] + g1 * vc[3 * i1 + 0] + g2 * vc[3 * i2 + 0]) / den;
        g  = (g0 * vc[3 * i0 + 1] + g1 * vc[3 * i1 + 1] + g2 * vc[3 * i2 + 1]) / den;
        bl = (g0 * vc[3 * i0 + 2] + g1 * vc[3 * i1 + 2] + g2 * vc[3 * i2 + 2]) / den;
    } else {
        r = bg[0]; g = bg[1]; bl = bg[2];
    }
    out[3 * p + 0] = r;
    out[3 * p + 1] = g;
    out[3 * p + 2] = bl;
}

// ---------------- launch ----------------------------------------------------
extern "C" void kernel_launch(void* const* d_in, const int* in_sizes, int n_in,
                              void* d_out, int out_size)
{
    const float* v     = (const float*)d_in[0];
    const float* vc    = (const float*)d_in[1];
    const int*   f     = (const int*)  d_in[2];
    const float* bg    = (const float*)d_in[3];
    const float* camf  = (const float*)d_in[4];
    const float* camc  = (const float*)d_in[5];
    const float* camt  = (const float*)d_in[6];
    const float* camrt = (const float*)d_in[7];

    int B = out_size / (NPIX * 3);
    int V = in_sizes[1] / 3;
    int F = in_sizes[2] / 3;
    int nchunks = (F + CHUNK - 1) / CHUNK;

    for (int b = 0; b < B; b++) {
        vertex_kernel<<<1, 256>>>(v + (size_t)b * V * 3, camf, camc, camt, camrt, V);
        tri_kernel<<<(F + 255) / 256, 256>>>(f, F);
        dim3 rgrid(NPIX / 256, nchunks);
        raster_kernel<<<rgrid, 256>>>(F);
        shade_kernel<<<NPIX / 256, 256>>>(f, vc, bg,
                                          (float*)d_out + (size_t)b * NPIX * 3,
                                          nchunks);
    }
}